// round 1
// baseline (speedup 1.0000x reference)
#include <cuda_runtime.h>
#include <cuda_bf16.h>

namespace {

constexpr int IMW = 1024;
constexpr int IMH = 1024;
constexpr int PY  = 8;   // output rows per thread

__device__ __forceinline__ void s2(float &a, float &b) {
    float t = fminf(a, b);
    b = fmaxf(a, b);
    a = t;
}

// Provably correct 9-comparator sort5: Batcher sort4 + insertion chain.
__device__ __forceinline__ void sort5(float v[5]) {
    s2(v[0], v[1]); s2(v[2], v[3]); s2(v[0], v[2]); s2(v[1], v[3]); s2(v[1], v[2]);
    s2(v[3], v[4]); s2(v[2], v[3]); s2(v[1], v[2]); s2(v[0], v[1]);
}

// Place min at m[0], max at m[K-1]; multiset preserved, middles intact.
template <int K>
__device__ __forceinline__ void minmaxK(float *m) {
    if constexpr ((K & 1) == 0) {
        #pragma unroll
        for (int i = 0; i < K; i += 2) s2(m[i], m[i + 1]);
        #pragma unroll
        for (int i = 2; i < K; i += 2) s2(m[0], m[i]);        // min chain (even slots)
        #pragma unroll
        for (int i = 1; i < K - 1; i += 2) s2(m[i], m[K - 1]); // max chain (odd slots)
    } else {
        #pragma unroll
        for (int i = 0; i + 1 < K; i += 2) s2(m[i], m[i + 1]);
        s2(m[K - 2], m[K - 1]);  // fold leftover into both chains
        #pragma unroll
        for (int i = 2; i <= K - 3; i += 2) s2(m[0], m[i]);
        s2(m[0], m[K - 2]);                                    // min done
        #pragma unroll
        for (int i = 1; i <= K - 4; i += 2) s2(m[i], m[K - 1]); // max done
    }
}

__device__ __forceinline__ float med3f(float a, float b, float c) {
    return fmaxf(fminf(a, b), fminf(fmaxf(a, b), c));
}

__global__ void __launch_bounds__(128)
median5x5_kernel(const float* __restrict__ in, float* __restrict__ out) {
    const int x  = blockIdx.x * 32 + threadIdx.x;
    const int y0 = (blockIdx.y * 4 + threadIdx.y) * PY;
    const long imgoff = (long)blockIdx.z << 20;  // 1024*1024 per image
    const float* img = in + imgoff;
    float* outp = out + imgoff + x;

    const bool okm2 = (x >= 2);
    const bool okm1 = (x >= 1);
    const bool okp1 = (x <= IMW - 2);
    const bool okp2 = (x <= IMW - 3);

    auto load_row = [&](int yy, float v[5]) {
        if ((unsigned)yy < (unsigned)IMH) {
            const float* p = img + yy * IMW + x;
            v[0] = okm2 ? __ldg(p - 2) : 0.0f;
            v[1] = okm1 ? __ldg(p - 1) : 0.0f;
            v[2] = __ldg(p);
            v[3] = okp1 ? __ldg(p + 1) : 0.0f;
            v[4] = okp2 ? __ldg(p + 2) : 0.0f;
        } else {
            v[0] = v[1] = v[2] = v[3] = v[4] = 0.0f;
        }
    };

    // Sorted horizontal 5-windows for input rows y-2 .. y+1 (reused down the strip).
    float r0[5], r1[5], r2[5], r3[5], r4[5];
    load_row(y0 - 2, r0); sort5(r0);
    load_row(y0 - 1, r1); sort5(r1);
    load_row(y0 + 0, r2); sort5(r2);
    load_row(y0 + 1, r3); sort5(r3);

    #pragma unroll
    for (int p = 0; p < PY; ++p) {
        load_row(y0 + 2 + p, r4); sort5(r4);   // only NEW row sorted per pixel

        // Column sorts of the row-sorted 5x5 -> doubly sorted matrix.
        float c0[5] = { r0[0], r1[0], r2[0], r3[0], r4[0] }; sort5(c0);
        float c1[5] = { r0[1], r1[1], r2[1], r3[1], r4[1] }; sort5(c1);
        float c2[5] = { r0[2], r1[2], r2[2], r3[2], r4[2] }; sort5(c2);
        float c3[5] = { r0[3], r1[3], r2[3], r3[3], r4[3] }; sort5(c3);
        float c4[5] = { r0[4], r1[4], r2[4], r3[4], r4[4] }; sort5(c4);

        // Median of 25 == median of the 13 doubly-sorted candidates:
        // (i,j) with (i+1)(j+1)<=13 and (5-i)(5-j)<=13, i = rank in column j.
        // Forgetful selection, buffer 8 (safe: 8 >= floor(13/2)+2).
        float m[8] = { c3[0], c4[0], c2[1], c3[1], c4[1], c1[2], c2[2], c3[2] };
        minmaxK<8>(m);
        m[7] = c0[3]; minmaxK<7>(m + 1);
        m[7] = c1[3]; minmaxK<6>(m + 2);
        m[7] = c2[3]; minmaxK<5>(m + 3);
        m[7] = c0[4]; minmaxK<4>(m + 4);
        m[7] = c1[4];
        float med = med3f(m[5], m[6], m[7]);

        outp[(y0 + p) * IMW] = med;

        // Slide the window down one row (register renaming under full unroll).
        #pragma unroll
        for (int j = 0; j < 5; ++j) {
            r0[j] = r1[j]; r1[j] = r2[j]; r2[j] = r3[j]; r3[j] = r4[j];
        }
    }
}

}  // namespace

extern "C" void kernel_launch(void* const* d_in, const int* in_sizes, int n_in,
                              void* d_out, int out_size) {
    const float* x = (const float*)d_in[0];
    float* out = (float*)d_out;
    const int nimg = out_size / (IMW * IMH);   // B*C = 8
    dim3 block(32, 4, 1);
    dim3 grid(IMW / 32, IMH / (4 * PY), nimg);
    median5x5_kernel<<<grid, block>>>(x, out);
}

// round 2
// speedup vs baseline: 1.1846x; 1.1846x over previous
#include <cuda_runtime.h>
#include <cuda_bf16.h>

namespace {

constexpr int IMW = 1024;
constexpr int IMH = 1024;
constexpr int PY  = 16;   // output rows per thread

__device__ __forceinline__ void s2(float &a, float &b) {
    float t = fminf(a, b);
    b = fmaxf(a, b);
    a = t;
}

// Provably correct 9-comparator sort5: Batcher sort4 + insertion chain.
__device__ __forceinline__ void sort5(float v[5]) {
    s2(v[0], v[1]); s2(v[2], v[3]); s2(v[0], v[2]); s2(v[1], v[3]); s2(v[1], v[2]);
    s2(v[3], v[4]); s2(v[2], v[3]); s2(v[1], v[2]); s2(v[0], v[1]);
}

// ---- Partial rank-set selectors (6 comparators each). Multiset-exact. ----

// top-2 multiset of {a0..a4} -> (o0,o1)
// sort4 prefix: a0=min4, a3=max4, a1/a2 middles. s2(a1,a2): a1 = 2nd-min4
// (has >=2 elements above -> not top-2, eliminated). s2(a2,a4): min of the
// pair is <= a3 as well -> eliminated. Kept {a3, a4} = top-2.
__device__ __forceinline__ void top2of5(float a0, float a1, float a2, float a3, float a4,
                                        float &o0, float &o1) {
    s2(a0, a1); s2(a2, a3); s2(a0, a2); s2(a1, a3); s2(a1, a2); s2(a2, a4);
    o0 = a3; o1 = a4;
}

// bottom-2 multiset -> (o0,o1). Mirror of top2of5.
__device__ __forceinline__ void bot2of5(float a0, float a1, float a2, float a3, float a4,
                                        float &o0, float &o1) {
    s2(a0, a1); s2(a2, a3); s2(a0, a2); s2(a1, a3); s2(a1, a2); s2(a1, a4);
    o0 = a0; o1 = a1;
}

// top-3 multiset -> (o0,o1,o2).
// sort4 prefix eliminates a0 = min4 (rank<=1 of 5). Then the remaining
// 2nd-smallest overall is min(2ndmin4, a4) = min(min(a1,a2), a4):
// s2(a1,a2); s2(a1,a4) eliminates it. Kept {a2, a3, a4}.
__device__ __forceinline__ void top3of5(float a0, float a1, float a2, float a3, float a4,
                                        float &o0, float &o1, float &o2) {
    s2(a0, a1); s2(a2, a3); s2(a0, a2); s2(a1, a3); s2(a1, a2); s2(a1, a4);
    o0 = a2; o1 = a3; o2 = a4;
}

// bottom-3 multiset -> (o0,o1,o2). Mirror: eliminates max4 and max(3rdmin4, a4).
__device__ __forceinline__ void bot3of5(float a0, float a1, float a2, float a3, float a4,
                                        float &o0, float &o1, float &o2) {
    s2(a0, a1); s2(a2, a3); s2(a0, a2); s2(a1, a3); s2(a1, a2); s2(a2, a4);
    o0 = a0; o1 = a1; o2 = a2;
}

// middle-3 multiset -> (o0,o1,o2): place global min/max at ends (6 comparators).
__device__ __forceinline__ void mid3of5(float a0, float a1, float a2, float a3, float a4,
                                        float &o0, float &o1, float &o2) {
    s2(a0, a1); s2(a2, a3); s2(a3, a4);   // a4 = max(a2,a3,a4)
    s2(a0, a2); s2(a0, a3);               // a0 = global min
    s2(a1, a4);                           // a4 = global max
    o0 = a1; o1 = a2; o2 = a3;
}

// Place min at m[0], max at m[K-1]; multiset preserved, middles intact.
template <int K>
__device__ __forceinline__ void minmaxK(float *m) {
    if constexpr ((K & 1) == 0) {
        #pragma unroll
        for (int i = 0; i < K; i += 2) s2(m[i], m[i + 1]);
        #pragma unroll
        for (int i = 2; i < K; i += 2) s2(m[0], m[i]);
        #pragma unroll
        for (int i = 1; i < K - 1; i += 2) s2(m[i], m[K - 1]);
    } else {
        #pragma unroll
        for (int i = 0; i + 1 < K; i += 2) s2(m[i], m[i + 1]);
        s2(m[K - 2], m[K - 1]);
        #pragma unroll
        for (int i = 2; i <= K - 3; i += 2) s2(m[0], m[i]);
        s2(m[0], m[K - 2]);
        #pragma unroll
        for (int i = 1; i <= K - 4; i += 2) s2(m[i], m[K - 1]);
    }
}

__device__ __forceinline__ float med3f(float a, float b, float c) {
    return fmaxf(fminf(a, b), fminf(fmaxf(a, b), c));
}

__global__ void __launch_bounds__(128)
median5x5_kernel(const float* __restrict__ in, float* __restrict__ out) {
    const int x  = blockIdx.x * 32 + threadIdx.x;
    const int y0 = (blockIdx.y * 4 + threadIdx.y) * PY;
    const long imgoff = (long)blockIdx.z << 20;  // 1024*1024 per image
    const float* img = in + imgoff;
    float* outp = out + imgoff + x;

    const bool okm2 = (x >= 2);
    const bool okm1 = (x >= 1);
    const bool okp1 = (x <= IMW - 2);
    const bool okp2 = (x <= IMW - 3);

    auto load_row = [&](int yy, float v[5]) {
        if ((unsigned)yy < (unsigned)IMH) {
            const float* p = img + yy * IMW + x;
            v[0] = okm2 ? __ldg(p - 2) : 0.0f;
            v[1] = okm1 ? __ldg(p - 1) : 0.0f;
            v[2] = __ldg(p);
            v[3] = okp1 ? __ldg(p + 1) : 0.0f;
            v[4] = okp2 ? __ldg(p + 2) : 0.0f;
        } else {
            v[0] = v[1] = v[2] = v[3] = v[4] = 0.0f;
        }
    };

    // Sorted horizontal 5-windows for input rows y-2 .. y+1 (reused down the strip).
    float r0[5], r1[5], r2[5], r3[5], r4[5];
    load_row(y0 - 2, r0); sort5(r0);
    load_row(y0 - 1, r1); sort5(r1);
    load_row(y0 + 0, r2); sort5(r2);
    load_row(y0 + 1, r3); sort5(r3);

    #pragma unroll
    for (int p = 0; p < PY; ++p) {
        load_row(y0 + 2 + p, r4); sort5(r4);   // only NEW row sorted per pixel

        // Median of 25 == median of 13 candidates of the doubly-sorted matrix:
        // col j keeps ranks: j=0:{3,4} j=1:{2,3,4} j=2:{1,2,3} j=3:{0,1,2} j=4:{0,1}.
        // Rank-set extraction (6 comparators per column) instead of full sort5.
        float t0a, t0b;
        top2of5(r0[0], r1[0], r2[0], r3[0], r4[0], t0a, t0b);
        float t1a, t1b, t1c;
        top3of5(r0[1], r1[1], r2[1], r3[1], r4[1], t1a, t1b, t1c);
        float t2a, t2b, t2c;
        mid3of5(r0[2], r1[2], r2[2], r3[2], r4[2], t2a, t2b, t2c);
        float t3a, t3b, t3c;
        bot3of5(r0[3], r1[3], r2[3], r3[3], r4[3], t3a, t3b, t3c);
        float t4a, t4b;
        bot2of5(r0[4], r1[4], r2[4], r3[4], r4[4], t4a, t4b);

        // Forgetful selection of median-of-13, buffer 8 (safe: 8 >= floor(13/2)+2).
        float m[8] = { t0a, t0b, t1a, t1b, t1c, t2a, t2b, t2c };
        minmaxK<8>(m);
        m[7] = t3a; minmaxK<7>(m + 1);
        m[7] = t3b; minmaxK<6>(m + 2);
        m[7] = t3c; minmaxK<5>(m + 3);
        m[7] = t4a; minmaxK<4>(m + 4);
        m[7] = t4b;
        float med = med3f(m[5], m[6], m[7]);

        outp[(y0 + p) * IMW] = med;

        // Slide the window down one row (register renaming under full unroll).
        #pragma unroll
        for (int j = 0; j < 5; ++j) {
            r0[j] = r1[j]; r1[j] = r2[j]; r2[j] = r3[j]; r3[j] = r4[j];
        }
    }
}

}  // namespace

extern "C" void kernel_launch(void* const* d_in, const int* in_sizes, int n_in,
                              void* d_out, int out_size) {
    const float* x = (const float*)d_in[0];
    float* out = (float*)d_out;
    const int nimg = out_size / (IMW * IMH);   // B*C = 8
    dim3 block(32, 4, 1);
    dim3 grid(IMW / 32, IMH / (4 * PY), nimg);
    median5x5_kernel<<<grid, block>>>(x, out);
}

// round 3
// speedup vs baseline: 1.2590x; 1.0628x over previous
#include <cuda_runtime.h>
#include <cuda_bf16.h>

namespace {

constexpr int IMW = 1024;
constexpr int IMH = 1024;
constexpr int PY  = 16;   // output rows per thread (processed in vertical pairs)

__device__ __forceinline__ void s2(float &a, float &b) {
    float t = fminf(a, b);
    b = fmaxf(a, b);
    a = t;
}

// 9-comparator sort5 (Batcher sort4 + insertion chain).
__device__ __forceinline__ void sort5(float v[5]) {
    s2(v[0], v[1]); s2(v[2], v[3]); s2(v[0], v[2]); s2(v[1], v[3]); s2(v[1], v[2]);
    s2(v[3], v[4]); s2(v[2], v[3]); s2(v[1], v[2]); s2(v[0], v[1]);
}

// 5-comparator sort4.
__device__ __forceinline__ void sort4(float &a, float &b, float &c, float &d) {
    s2(a, b); s2(c, d); s2(a, c); s2(b, d); s2(b, c);
}

// Place min at m[0], max at m[K-1]; multiset preserved, middles intact.
template <int K>
__device__ __forceinline__ void minmaxK(float *m) {
    if constexpr ((K & 1) == 0) {
        #pragma unroll
        for (int i = 0; i < K; i += 2) s2(m[i], m[i + 1]);
        #pragma unroll
        for (int i = 2; i < K; i += 2) s2(m[0], m[i]);
        #pragma unroll
        for (int i = 1; i < K - 1; i += 2) s2(m[i], m[K - 1]);
    } else {
        #pragma unroll
        for (int i = 0; i + 1 < K; i += 2) s2(m[i], m[i + 1]);
        s2(m[K - 2], m[K - 1]);
        #pragma unroll
        for (int i = 2; i <= K - 3; i += 2) s2(m[0], m[i]);
        s2(m[0], m[K - 2]);
        #pragma unroll
        for (int i = 1; i <= K - 4; i += 2) s2(m[i], m[K - 1]);
    }
}

__device__ __forceinline__ float med3f(float a, float b, float c) {
    return fmaxf(fminf(a, b), fminf(fmaxf(a, b), c));
}

// Median of the 13 doubly-sorted candidates.
// Known preorders exploited in stage 1: t1a<=t1b (col1 q2<=q3), t2a<=t2b (col2 q1<=q2).
__device__ __forceinline__ float median13(
    float t0a, float t0b,                     // col0 top2 (unordered)
    float t1a, float t1b, float t1c,          // col1 top3, t1a<=t1b
    float t2a, float t2b, float t2c,          // col2 mid3, t2a<=t2b
    float t3a, float t3b, float t3c,          // col3 bot3
    float t4a, float t4b)                     // col4 bot2
{
    // minmax of 8 = {t0a,t0b,t1a,t1b,t1c,t2a,t2b,t2c} in 8 swaps.
    float l2 = t0a, h2 = t0b; s2(l2, h2);
    float l3 = t1c, h3 = t2c; s2(l3, h3);
    float l0 = t1a, l1 = t2a, h0 = t1b, h1 = t2b;
    s2(l0, l1); s2(l0, l2); s2(l0, l3);   // l0 = min of 8 (dropped)
    s2(h0, h1); s2(h1, h2); s2(h2, h3);   // h3 = max of 8 (dropped)

    float m[7];
    m[0] = l1; m[1] = l2; m[2] = l3; m[3] = h0; m[4] = h1; m[5] = h2;
    m[6] = t3a; minmaxK<7>(m);       // middle: m[1..5]
    m[6] = t3b; minmaxK<6>(m + 1);   // middle: m[2..5]
    m[6] = t3c; minmaxK<5>(m + 2);   // middle: m[3..5]
    m[6] = t4a; minmaxK<4>(m + 3);   // middle: m[4..5]
    m[6] = t4b;
    return med3f(m[4], m[5], m[6]);
}

__global__ void __launch_bounds__(128)
median5x5_kernel(const float* __restrict__ in, float* __restrict__ out) {
    const int x  = blockIdx.x * 32 + threadIdx.x;
    const int y0 = (blockIdx.y * 4 + threadIdx.y) * PY;
    const long imgoff = (long)blockIdx.z << 20;  // 1024*1024 per image
    const float* img = in + imgoff;
    float* outp = out + imgoff + x;

    const bool okm2 = (x >= 2);
    const bool okm1 = (x >= 1);
    const bool okp1 = (x <= IMW - 2);
    const bool okp2 = (x <= IMW - 3);

    auto load_row = [&](int yy, float v[5]) {
        if ((unsigned)yy < (unsigned)IMH) {
            const float* p = img + yy * IMW + x;
            v[0] = okm2 ? __ldg(p - 2) : 0.0f;
            v[1] = okm1 ? __ldg(p - 1) : 0.0f;
            v[2] = __ldg(p);
            v[3] = okp1 ? __ldg(p + 1) : 0.0f;
            v[4] = okp2 ? __ldg(p + 2) : 0.0f;
        } else {
            v[0] = v[1] = v[2] = v[3] = v[4] = 0.0f;
        }
    };

    // Sorted horizontal 5-windows. For the pair (y, y+1):
    // r0 = y-2 (private to pixel A), r1..r4 = y-1..y+2 (common), r5 = y+3 (private to B).
    float r0[5], r1[5], r2[5], r3[5], r4[5], r5[5];
    load_row(y0 - 2, r0); sort5(r0);
    load_row(y0 - 1, r1); sort5(r1);
    load_row(y0 + 0, r2); sort5(r2);
    load_row(y0 + 1, r3); sort5(r3);

    #pragma unroll 1
    for (int p = 0; p < PY; p += 2) {
        const int y = y0 + p;
        load_row(y + 2, r4); sort5(r4);
        load_row(y + 3, r5); sort5(r5);

        // Shared per-column sort4 of the 4 common rows.
        float q[5][4];
        #pragma unroll
        for (int j = 0; j < 5; ++j) {
            q[j][0] = r1[j]; q[j][1] = r2[j]; q[j][2] = r3[j]; q[j][3] = r4[j];
            sort4(q[j][0], q[j][1], q[j][2], q[j][3]);
        }

        // O(1) merge of each pixel's private element into the required rank sets.
        // col j keeps column-ranks: j=0:{3,4} j=1:{2,3,4} j=2:{1,2,3} j=3:{0,1,2} j=4:{0,1}.
        #pragma unroll
        for (int pix = 0; pix < 2; ++pix) {
            const float* rp = pix ? r5 : r0;
            float a0 = rp[0], a1 = rp[1], a2 = rp[2], a3 = rp[3], a4 = rp[4];

            float t0a = q[0][3];
            float t0b = fmaxf(q[0][2], a0);

            float t1a = q[1][2], t1b = q[1][3];
            float t1c = fmaxf(q[1][1], a1);

            float t2a = q[2][1], t2b = q[2][2];
            float t2c = fminf(fmaxf(a2, q[2][0]), q[2][3]);   // clamp

            float t3a = q[3][0], t3b = q[3][1];
            float t3c = fminf(q[3][2], a3);

            float t4a = q[4][0];
            float t4b = fminf(q[4][1], a4);

            float med = median13(t0a, t0b, t1a, t1b, t1c,
                                 t2a, t2b, t2c, t3a, t3b, t3c, t4a, t4b);
            outp[(y + pix) * IMW] = med;
        }

        // Slide window down two rows.
        #pragma unroll
        for (int j = 0; j < 5; ++j) {
            r0[j] = r2[j]; r1[j] = r3[j]; r2[j] = r4[j]; r3[j] = r5[j];
        }
    }
}

}  // namespace

extern "C" void kernel_launch(void* const* d_in, const int* in_sizes, int n_in,
                              void* d_out, int out_size) {
    const float* x = (const float*)d_in[0];
    float* out = (float*)d_out;
    const int nimg = out_size / (IMW * IMH);   // B*C = 8
    dim3 block(32, 4, 1);
    dim3 grid(IMW / 32, IMH / (4 * PY), nimg);
    median5x5_kernel<<<grid, block>>>(x, out);
}